// round 10
// baseline (speedup 1.0000x reference)
#include <cuda_runtime.h>
#include <cstdint>

#define NUM_JOINT 19
#define ROOT_SCALE 200.0f
#define BLOCK 32
#define TILE_FLOATS (BLOCK * NUM_JOINT * 4)   // 2432
#define TILE_BYTES  (TILE_FLOATS * 4)         // 9728
#define GRID 1628                              // 148 SMs * 11 CTAs

__constant__ float c_off[NUM_JOINT * 16];

__device__ __forceinline__ void tma_load(uint32_t sdst, const float* gsrc, uint32_t mb) {
    asm volatile("mbarrier.arrive.expect_tx.shared.b64 _, [%0], %1;"
                 :: "r"(mb), "r"((uint32_t)TILE_BYTES) : "memory");
    asm volatile("cp.async.bulk.shared::cta.global.mbarrier::complete_tx::bytes "
                 "[%0], [%1], %2, [%3];"
                 :: "r"(sdst), "l"(gsrc), "r"((uint32_t)TILE_BYTES), "r"(mb) : "memory");
}

__global__ __launch_bounds__(BLOCK, 11)
void fk_kernel(const float* __restrict__ root,
               const float* __restrict__ joint,
               float* __restrict__ out,
               int ntiles)
{
    __shared__ alignas(16) float sload[TILE_FLOATS];   // TMA-load landing zone
    __shared__ alignas(16) float sstore[TILE_FLOATS];  // bulk-store staging zone
    __shared__ alignas(8)  unsigned long long mbar;

    const int t = threadIdx.x;
    const uint32_t sl_addr = (uint32_t)__cvta_generic_to_shared(sload);
    const uint32_t ss_addr = (uint32_t)__cvta_generic_to_shared(sstore);
    const uint32_t mb_addr = (uint32_t)__cvta_generic_to_shared(&mbar);

    if (t == 0)
        asm volatile("mbarrier.init.shared.b64 [%0], 1;" :: "r"(mb_addr) : "memory");
    __syncwarp();

    const int parents[NUM_JOINT] = {-1,0,1,2,3,2,5,6,7,2,9,10,11,0,13,14,0,16,17};

    // Prologue: load first tile.
    if (t == 0 && blockIdx.x < ntiles)
        tma_load(sl_addr, joint + (size_t)blockIdx.x * TILE_FLOATS, mb_addr);

    int it = 0;
    for (int tile = blockIdx.x; tile < ntiles; tile += GRID, it++) {
        // Root fetch overlaps the load-wait window.
        const long long b = (long long)tile * BLOCK + t;
        const float rx = __ldg(&root[b * 3 + 0]) * ROOT_SCALE;
        const float ry = __ldg(&root[b * 3 + 1]) * ROOT_SCALE;
        const float rz = __ldg(&root[b * 3 + 2]) * ROOT_SCALE;

        // Wait for this tile's data (phase flips every iteration).
        asm volatile(
            "{\n\t.reg .pred P;\n\t"
            "W%=:\n\t"
            "mbarrier.try_wait.parity.acquire.cta.shared::cta.b64 P, [%0], %1, 0x989680;\n\t"
            "@!P bra W%=;\n\t}"
            :: "r"(mb_addr), "r"((uint32_t)(it & 1)) : "memory");

        // Slurp all 19 quats into registers, freeing the load buffer.
        const float* row = &sload[t * (NUM_JOINT * 4)];   // 76-float stride: conflict-free
        float4 q[NUM_JOINT];
        #pragma unroll
        for (int j = 0; j < NUM_JOINT; j++)
            q[j] = *(const float4*)&row[j * 4];
        __syncwarp();

        // Prefetch next tile into the SAME load buffer; it flies during compute.
        if (t == 0 && tile + GRID < ntiles) {
            asm volatile("fence.proxy.async.shared::cta;" ::: "memory");
            tma_load(sl_addr, joint + (size_t)(tile + GRID) * TILE_FLOATS, mb_addr);
        }

        // ---- FK chain via composite (non-unit) quaternions, all in registers ----
        float gw[NUM_JOINT], gx[NUM_JOINT], gy[NUM_JOINT], gz[NUM_JOINT];
        float ox[NUM_JOINT], oy[NUM_JOINT], oz[NUM_JOINT];
        #pragma unroll
        for (int j = 0; j < NUM_JOINT; j++) {
            float aw, ax, ay, az;
            if (j == 0) {
                aw = q[0].x; ax = q[0].y; ay = q[0].z; az = q[0].w;
            } else {
                const int p = parents[j];
                const float bw = q[j].x, bx = q[j].y, by = q[j].z, bz = q[j].w;
                aw = gw[p]*bw - gx[p]*bx - gy[p]*by - gz[p]*bz;
                ax = gw[p]*bx + gx[p]*bw + gy[p]*bz - gz[p]*by;
                ay = gw[p]*by - gx[p]*bz + gy[p]*bw + gz[p]*bx;
                az = gw[p]*bz + gx[p]*by - gy[p]*bx + gz[p]*bw;
            }
            gw[j] = aw; gx[j] = ax; gy[j] = ay; gz[j] = az;

            const float tx = c_off[j * 16 + 3];
            const float ty = c_off[j * 16 + 7];
            const float tz = c_off[j * 16 + 11];

            const float n  = aw*aw + ax*ax + ay*ay + az*az;
            const float sc = __fdividef(2.0f, n);

            const float cx = ay*tz - az*ty;
            const float cy = az*tx - ax*tz;
            const float cz = ax*ty - ay*tx;

            const float dx = aw*cx + (ay*cz - az*cy);
            const float dy = aw*cy + (az*cx - ax*cz);
            const float dz = aw*cz + (ax*cy - ay*cx);

            float vx = tx + sc * dx;
            float vy = ty + sc * dy;
            float vz = tz + sc * dz;
            if (j > 0) {
                const int p = parents[j];
                vx += ox[p]; vy += oy[p]; vz += oz[p];
            }
            ox[j] = vx; oy[j] = vy; oz[j] = vz;
        }

        // Previous bulk store must be fully drained before we overwrite sstore.
        // It has had at least one full compute phase -> near-zero stall.
        if (t == 0)
            asm volatile("cp.async.bulk.wait_group 0;" ::: "memory");
        __syncwarp();

        float* srow = &sstore[t * (NUM_JOINT * 4)];
        #pragma unroll
        for (int j = 0; j < NUM_JOINT; j++) {
            float4 o;
            o.x = ox[j] + rx; o.y = oy[j] + ry; o.z = oz[j] + rz; o.w = 1.0f;
            *(float4*)&srow[j * 4] = o;
        }
        __syncwarp();

        if (t == 0) {
            asm volatile("fence.proxy.async.shared::cta;" ::: "memory");
            float* gdst = out + (size_t)tile * TILE_FLOATS;
            asm volatile("cp.async.bulk.global.shared::cta.bulk_group [%0], [%1], %2;"
                         :: "l"(gdst), "r"(ss_addr), "r"((uint32_t)TILE_BYTES) : "memory");
            asm volatile("cp.async.bulk.commit_group;" ::: "memory");
        }
    }

    // smem must outlive the final store.
    if (t == 0)
        asm volatile("cp.async.bulk.wait_group 0;" ::: "memory");
}

extern "C" void kernel_launch(void* const* d_in, const int* in_sizes, int n_in,
                              void* d_out, int out_size)
{
    const float* root    = (const float*)d_in[0];   // (B, 3)
    const float* joint   = (const float*)d_in[1];   // (B, 76)
    const float* offsets = (const float*)d_in[2];   // (19, 4, 4)
    float* out = (float*)d_out;                     // (B, 19, 4)

    cudaMemcpyToSymbolAsync(c_off, offsets, NUM_JOINT * 16 * sizeof(float),
                            0, cudaMemcpyDeviceToDevice, 0);

    const int B = in_sizes[1] / (NUM_JOINT * 4);    // 262144
    const int ntiles = B / BLOCK;                   // 8192
    fk_kernel<<<GRID, BLOCK>>>(root, joint, out, ntiles);
}

// round 11
// speedup vs baseline: 1.0292x; 1.0292x over previous
#include <cuda_runtime.h>
#include <cstdint>

#define NUM_JOINT 19
#define ROOT_SCALE 200.0f
#define BLOCK 32
#define TILE_FLOATS (BLOCK * NUM_JOINT * 4)   // 2432
#define TILE_BYTES  (TILE_FLOATS * 4)         // 9728
#define NCTA_SM 7
#define GRID (148 * NCTA_SM)                   // 1036 persistent CTAs

__constant__ float c_off[NUM_JOINT * 16];

__device__ __forceinline__ void tma_load(uint32_t sdst, const float* gsrc, uint32_t mb) {
    asm volatile("mbarrier.arrive.expect_tx.shared.b64 _, [%0], %1;"
                 :: "r"(mb), "r"((uint32_t)TILE_BYTES) : "memory");
    asm volatile("cp.async.bulk.shared::cta.global.mbarrier::complete_tx::bytes "
                 "[%0], [%1], %2, [%3];"
                 :: "r"(sdst), "l"(gsrc), "r"((uint32_t)TILE_BYTES), "r"(mb) : "memory");
}

__global__ __launch_bounds__(BLOCK, NCTA_SM)
void fk_kernel(const float* __restrict__ root,
               const float* __restrict__ joint,
               float* __restrict__ out,
               int ntiles)
{
    __shared__ alignas(16) float s[3][TILE_FLOATS];        // 29184 B, rotating ring
    __shared__ alignas(8)  unsigned long long mbar[3];

    const int t = threadIdx.x;
    const uint32_t s0 = (uint32_t)__cvta_generic_to_shared(&s[0][0]);
    const uint32_t m0 = (uint32_t)__cvta_generic_to_shared(&mbar[0]);

    if (t == 0) {
        #pragma unroll
        for (int k = 0; k < 3; k++)
            asm volatile("mbarrier.init.shared.b64 [%0], 1;" :: "r"(m0 + k * 8) : "memory");
    }
    __syncwarp();

    const int parents[NUM_JOINT] = {-1,0,1,2,3,2,5,6,7,2,9,10,11,0,13,14,0,16,17};

    // Prologue: depth-2 prefetch of tiles it=0,1 into bufs 0,1.
    if (t == 0) {
        if (blockIdx.x < ntiles)
            tma_load(s0, joint + (size_t)blockIdx.x * TILE_FLOATS, m0);
        if (blockIdx.x + GRID < ntiles)
            tma_load(s0 + TILE_BYTES,
                     joint + (size_t)(blockIdx.x + GRID) * TILE_FLOATS, m0 + 8);
    }

    int it = 0;
    for (int tile = blockIdx.x; tile < ntiles; tile += GRID, it++) {
        const int buf = it % 3;
        const uint32_t parity = (uint32_t)((it / 3) & 1);
        const uint32_t sbuf = s0 + buf * TILE_BYTES;

        // Root fetch overlaps the load-wait window.
        const long long b = (long long)tile * BLOCK + t;
        const float rx = __ldg(&root[b * 3 + 0]) * ROOT_SCALE;
        const float ry = __ldg(&root[b * 3 + 1]) * ROOT_SCALE;
        const float rz = __ldg(&root[b * 3 + 2]) * ROOT_SCALE;

        // Wait for this tile (load was issued 2 iterations ago).
        asm volatile(
            "{\n\t.reg .pred P;\n\t"
            "W%=:\n\t"
            "mbarrier.try_wait.parity.acquire.cta.shared::cta.b64 P, [%0], %1, 0x989680;\n\t"
            "@!P bra W%=;\n\t}"
            :: "r"(m0 + buf * 8), "r"(parity) : "memory");

        // Slurp all 19 quats into registers; frees buf for the result writes.
        const float* row = &s[buf][t * (NUM_JOINT * 4)];   // 76-float stride: conflict-free
        float4 q[NUM_JOINT];
        #pragma unroll
        for (int j = 0; j < NUM_JOINT; j++)
            q[j] = *(const float4*)&row[j * 4];
        __syncwarp();

        // Depth-2 prefetch: tile it+2 -> buf (it+2)%3. That buffer's last store
        // (tile it-1) committed at the end of the previous iteration; drain it.
        if (t == 0 && tile + 2 * GRID < ntiles) {
            asm volatile("cp.async.bulk.wait_group 0;" ::: "memory");
            const int nb = (it + 2) % 3;
            tma_load(s0 + nb * TILE_BYTES,
                     joint + (size_t)(tile + 2 * GRID) * TILE_FLOATS, m0 + nb * 8);
        }

        // ---- FK chain via composite (non-unit) quaternions, in registers ----
        float gw[NUM_JOINT], gx[NUM_JOINT], gy[NUM_JOINT], gz[NUM_JOINT];
        float ox[NUM_JOINT], oy[NUM_JOINT], oz[NUM_JOINT];
        #pragma unroll
        for (int j = 0; j < NUM_JOINT; j++) {
            float aw, ax, ay, az;
            if (j == 0) {
                aw = q[0].x; ax = q[0].y; ay = q[0].z; az = q[0].w;
            } else {
                const int p = parents[j];
                const float bw = q[j].x, bx = q[j].y, by = q[j].z, bz = q[j].w;
                aw = gw[p]*bw - gx[p]*bx - gy[p]*by - gz[p]*bz;
                ax = gw[p]*bx + gx[p]*bw + gy[p]*bz - gz[p]*by;
                ay = gw[p]*by - gx[p]*bz + gy[p]*bw + gz[p]*bx;
                az = gw[p]*bz + gx[p]*by - gy[p]*bx + gz[p]*bw;
            }
            gw[j] = aw; gx[j] = ax; gy[j] = ay; gz[j] = az;

            const float tx = c_off[j * 16 + 3];
            const float ty = c_off[j * 16 + 7];
            const float tz = c_off[j * 16 + 11];

            const float n  = aw*aw + ax*ax + ay*ay + az*az;
            const float sc = __fdividef(2.0f, n);

            const float cx = ay*tz - az*ty;
            const float cy = az*tx - ax*tz;
            const float cz = ax*ty - ay*tx;

            const float dx = aw*cx + (ay*cz - az*cy);
            const float dy = aw*cy + (az*cx - ax*cz);
            const float dz = aw*cz + (ax*cy - ay*cx);

            float vx = tx + sc * dx;
            float vy = ty + sc * dy;
            float vz = tz + sc * dz;
            if (j > 0) {
                const int p = parents[j];
                vx += ox[p]; vy += oy[p]; vz += oz[p];
            }
            ox[j] = vx; oy[j] = vy; oz[j] = vz;
        }

        // Results overwrite this tile's buffer (slurped; its next TMA load is
        // tile it+3, issued next iteration AFTER wait_group drains this store).
        float* wrow = &s[buf][t * (NUM_JOINT * 4)];
        #pragma unroll
        for (int j = 0; j < NUM_JOINT; j++) {
            float4 o;
            o.x = ox[j] + rx; o.y = oy[j] + ry; o.z = oz[j] + rz; o.w = 1.0f;
            *(float4*)&wrow[j * 4] = o;
        }
        __syncwarp();

        if (t == 0) {
            asm volatile("fence.proxy.async.shared::cta;" ::: "memory");
            float* gdst = out + (size_t)tile * TILE_FLOATS;
            asm volatile("cp.async.bulk.global.shared::cta.bulk_group [%0], [%1], %2;"
                         :: "l"(gdst), "r"(sbuf), "r"((uint32_t)TILE_BYTES) : "memory");
            asm volatile("cp.async.bulk.commit_group;" ::: "memory");
        }
    }

    // smem must outlive the final store.
    if (t == 0)
        asm volatile("cp.async.bulk.wait_group 0;" ::: "memory");
}

extern "C" void kernel_launch(void* const* d_in, const int* in_sizes, int n_in,
                              void* d_out, int out_size)
{
    const float* root    = (const float*)d_in[0];   // (B, 3)
    const float* joint   = (const float*)d_in[1];   // (B, 76)
    const float* offsets = (const float*)d_in[2];   // (19, 4, 4)
    float* out = (float*)d_out;                     // (B, 19, 4)

    cudaMemcpyToSymbolAsync(c_off, offsets, NUM_JOINT * 16 * sizeof(float),
                            0, cudaMemcpyDeviceToDevice, 0);

    const int B = in_sizes[1] / (NUM_JOINT * 4);    // 262144
    const int ntiles = B / BLOCK;                   // 8192
    fk_kernel<<<GRID, BLOCK>>>(root, joint, out, ntiles);
}